// round 17
// baseline (speedup 1.0000x reference)
#include <cuda_runtime.h>
#include <cuda_bf16.h>
#include <math.h>
#include <float.h>
#include <stdint.h>

#define NK 8192      // 16*512
#define NQ 32768     // 16*2048

// ---- K path buffers ----
__device__ __nv_bfloat16 g_Bthi[8192u * 1536];
__device__ __nv_bfloat16 g_Btlo[8192u * 1536];
__device__ __nv_bfloat16 g_w1hi[1024u * 1536];
__device__ __nv_bfloat16 g_w1lo[1024u * 1536];
__device__ __nv_bfloat16 g_hThi[8192u * 1024];
__device__ __nv_bfloat16 g_hTlo[8192u * 1024];
__device__ __nv_bfloat16 g_w2hi[128u * 1024];
__device__ __nv_bfloat16 g_w2lo[128u * 1024];
__device__ float g_kf[80u * NK];
// ---- Q path buffers ----
__device__ __nv_bfloat16 g_BtQhi[32768u * 256];
__device__ __nv_bfloat16 g_BtQlo[32768u * 256];
__device__ __nv_bfloat16 g_qw1hi[256u * 256];
__device__ __nv_bfloat16 g_qw1lo[256u * 256];
__device__ __nv_bfloat16 g_q1hi[32768u * 256];
__device__ __nv_bfloat16 g_q1lo[32768u * 256];
__device__ __nv_bfloat16 g_qw2hi[128u * 256];
__device__ __nv_bfloat16 g_qw2lo[128u * 256];
__device__ __nv_bfloat16 g_q2hi[32768u * 128];
__device__ __nv_bfloat16 g_q2lo[32768u * 128];
__device__ __nv_bfloat16 g_qw3hi[128u * 128];
__device__ __nv_bfloat16 g_qw3lo[128u * 128];
__device__ float g_qf[80u * NQ];
// ---- attn transposed features + norms ----
__device__ __nv_bfloat16 g_qfThi[32768u * 128];
__device__ __nv_bfloat16 g_qfTlo[32768u * 128];
__device__ __nv_bfloat16 g_kfThi[8192u * 128];
__device__ __nv_bfloat16 g_kfTlo[8192u * 128];
__device__ float g_q2n[32768];
__device__ float g_k2n[8192];
// ---- padded biases ----
__device__ float g_qb1p[256];
__device__ float g_qb2p[128];
__device__ float g_qb3p[128];
__device__ float g_kb2p[128];

// =========================== PTX helpers (sm_80+ baseline) ===========================
__device__ __forceinline__ uint32_t smem_u32(const void* p) {
    return (uint32_t)__cvta_generic_to_shared(p);
}
#define SW128(x) ((x) ^ (((x) >> 3) & 0x70))
#define SW64(x)  ((x) ^ (((x) >> 3) & 0x30))

__device__ __forceinline__ void cpa16(uint32_t dst, const void* src) {
    asm volatile("cp.async.cg.shared.global [%0], [%1], 16;\n" :: "r"(dst), "l"(src));
}
#define CP_COMMIT() asm volatile("cp.async.commit_group;\n" ::: "memory")

__device__ __forceinline__ void ldsm4(uint32_t* r, uint32_t addr) {
    asm volatile("ldmatrix.sync.aligned.m8n8.x4.shared.b16 {%0,%1,%2,%3}, [%4];"
                 : "=r"(r[0]), "=r"(r[1]), "=r"(r[2]), "=r"(r[3]) : "r"(addr));
}

__device__ __forceinline__ void mma_bf16(float* c, const uint32_t* a, const uint32_t* b) {
    asm volatile(
        "mma.sync.aligned.m16n8k16.row.col.f32.bf16.bf16.f32 "
        "{%0,%1,%2,%3}, {%4,%5,%6,%7}, {%8,%9}, {%0,%1,%2,%3};\n"
        : "+f"(c[0]), "+f"(c[1]), "+f"(c[2]), "+f"(c[3])
        : "r"(a[0]), "r"(a[1]), "r"(a[2]), "r"(a[3]), "r"(b[0]), "r"(b[1]));
}

// FFMA-only sqrt: magic rsqrt + 2 Newton iterations (rel err ~4e-6). No MUFU.
__device__ __forceinline__ float sqrt_fast(float x) {
    float y = __int_as_float(0x5f3759dfu - (__float_as_int(x) >> 1));
    y = y * fmaf(-0.5f * x * y, y, 1.5f);
    y = y * fmaf(-0.5f * x * y, y, 1.5f);
    return x * y;
}

// FFMA-only exp (exp2 range reduction + deg-5 poly). Valid for x <= 0.
__device__ __forceinline__ float exp_fast(float x) {
    float t = x * 1.4426950408889634f;
    t = fmaxf(t, -126.0f);
    float fn = t + 12582912.0f;
    float n  = fn - 12582912.0f;
    float f  = t - n;
    float p  = 1.3333558e-3f;
    p = fmaf(p, f, 9.6181291e-3f);
    p = fmaf(p, f, 5.5504109e-2f);
    p = fmaf(p, f, 2.4022651e-1f);
    p = fmaf(p, f, 6.9314718e-1f);
    p = fmaf(p, f, 1.0f);
    float sc = __int_as_float(((int)n + 127) << 23);
    return p * sc;
}

// =========================== prep kernels ===========================
__global__ void split_pad2(const float* __restrict__ in, __nv_bfloat16* __restrict__ hi,
                           __nv_bfloat16* __restrict__ lo, int R, int C, int outC, int total)
{
    int idx = blockIdx.x * 256 + threadIdx.x;
    if (idx >= total) return;
    int row = idx / outC, col = idx - row * outC;
    float v = (row < R && col < C) ? in[row * C + col] : 0.f;
    __nv_bfloat16 h = __float2bfloat16(v);
    hi[idx] = h;
    lo[idx] = __float2bfloat16(v - __bfloat162float(h));
}

__global__ void pad_bias(const float* __restrict__ in, float* __restrict__ out, int C, int outC)
{
    int i = threadIdx.x;
    if (i < outC) out[i] = (i < C) ? in[i] : 0.f;
}

__global__ __launch_bounds__(256)
void build_Bt(const float* __restrict__ keys,
              __nv_bfloat16* __restrict__ bhi, __nv_bfloat16* __restrict__ blo)
{
    __shared__ float sk[64][131];
    const int tid = threadIdx.x;
    const int nt = blockIdx.x;
    const int cc = blockIdx.y * 64;
    const int b  = nt >> 2;
    const int t0 = (nt & 3) * 128;
    const int n0 = b * 512 + t0;

    for (int idx = tid; idx < 64 * 130; idx += 256) {
        int cl = idx / 130, tt = idx - cl * 130;
        int ts = t0 + tt - 1;
        sk[cl][tt] = ((unsigned)ts < 512u)
                     ? keys[((size_t)b * 512 + cc + cl) * 512 + ts] : 0.f;
    }
    __syncthreads();
    for (int idx = tid; idx < 128 * 192; idx += 256) {
        int tl = idx / 192, r = idx - tl * 192;
        int cl = r / 3, dt = r - cl * 3;
        float v = sk[cl][tl + dt];
        __nv_bfloat16 h = __float2bfloat16(v);
        size_t o = (size_t)(n0 + tl) * 1536 + cc * 3 + r;
        bhi[o] = h;
        blo[o] = __float2bfloat16(v - __bfloat162float(h));
    }
}

__global__ __launch_bounds__(256)
void build_BtQ(const float* __restrict__ queries,
               __nv_bfloat16* __restrict__ bhi, __nv_bfloat16* __restrict__ blo)
{
    __shared__ float sk[80][131];
    const int tid = threadIdx.x;
    const int nt = blockIdx.x;
    const int b  = nt >> 4;
    const int t0 = (nt & 15) * 128;
    const int n0 = b * 2048 + t0;

    for (int idx = tid; idx < 80 * 130; idx += 256) {
        int cl = idx / 130, tt = idx - cl * 130;
        int ts = t0 + tt - 1;
        sk[cl][tt] = ((unsigned)ts < 2048u)
                     ? queries[((size_t)b * 80 + cl) * 2048 + ts] : 0.f;
    }
    __syncthreads();
    for (int idx = tid; idx < 128 * 256; idx += 256) {
        int tl = idx >> 8, r = idx & 255;
        float v = 0.f;
        if (r < 240) {
            int cl = r / 3, dt = r - cl * 3;
            v = sk[cl][tl + dt];
        }
        __nv_bfloat16 h = __float2bfloat16(v);
        size_t o = (size_t)(n0 + tl) * 256 + r;
        bhi[o] = h;
        blo[o] = __float2bfloat16(v - __bfloat162float(h));
    }
}

// Transpose [80][N] fp32 -> [n][128] bf16 hi/lo (c padded to 128) + fp32 norms.
__global__ __launch_bounds__(256)
void cvtT(const float* __restrict__ src, int N,
          __nv_bfloat16* __restrict__ dhi, __nv_bfloat16* __restrict__ dlo,
          float* __restrict__ nrm)
{
    __shared__ float s[80][132];
    const int tid = threadIdx.x;
    const int n0 = blockIdx.x * 128;
    for (int q = tid; q < 80 * 32; q += 256) {
        int c = q >> 5, j = (q & 31) * 4;
        *(float4*)&s[c][j] = *(const float4*)&src[(size_t)c * N + n0 + j];
    }
    __syncthreads();
    for (int idx = tid; idx < 128 * 128; idx += 256) {
        int nl = idx >> 7, c = idx & 127;
        float v = (c < 80) ? s[c][nl] : 0.f;
        __nv_bfloat16 h = __float2bfloat16(v);
        size_t o = (size_t)(n0 + nl) * 128 + c;
        dhi[o] = h;
        dlo[o] = __float2bfloat16(v - __bfloat162float(h));
    }
    if (tid < 128) {
        float sum = 0.f;
        for (int c = 0; c < 80; c++) { float v = s[c][tid]; sum += v * v; }
        nrm[n0 + tid] = sum;
    }
}

// ===================== BIG-TILE bf16x3 GEMM for K-path GEMM1 =====================
// C[i][j] = sum_k A[i][k]*B[j][k], hi*hi + lo*hi + hi*lo.
// CTA tile 256x256, K-chunk 32 (64B rows, SW64 swizzle), 2-stage cp.async.
// 512 threads = 16 warps (4x4), warp tile 64x64. out = relu(C+bias[j]) -> bf16 pair.
// smem: stage s @ s*65536: Ahi@0 Alo@16384 Bhi@32768 Blo@49152 (16KB each). Total 128KB.
#define MMKB_SMEM 131072

__global__ __launch_bounds__(512)
void mmk_big(const __nv_bfloat16* __restrict__ aHi, const __nv_bfloat16* __restrict__ aLo,
             const __nv_bfloat16* __restrict__ bHi, const __nv_bfloat16* __restrict__ bLo,
             const float* __restrict__ bias,
             __nv_bfloat16* __restrict__ outHi, __nv_bfloat16* __restrict__ outLo,
             int Kdim, int ost)
{
    extern __shared__ __align__(1024) char smx[];
    const int tid  = threadIdx.x;
    const int wid  = tid >> 5, lane = tid & 31;
    const int nCh  = Kdim >> 5;                      // 32-wide chunks

    const int aRow0 = blockIdx.x * 256;
    const int bRow0 = blockIdx.y * 256;

    const int warp_i = (wid >> 2) * 64;
    const int warp_j = (wid & 3) * 64;

    const uint32_t sbase = smem_u32(smx);
    const uint32_t stg[2] = { sbase, sbase + 65536u };

    auto load_chunk = [&](int c, int s) {
        const uint32_t base = stg[s];
        const size_t cb = (size_t)c * 32;
#pragma unroll
        for (int it = 0; it < 8; it++) {
            int idx = tid + it * 512;                // 0..4095
            int mat = idx >> 10;                     // 0 Ahi,1 Alo,2 Bhi,3 Blo
            int rem = idx & 1023;
            int r   = rem >> 2;                      // 0..255
            int g   = rem & 3;                       // 16B group
            const __nv_bfloat16* srcm =
                (mat == 0) ? aHi : (mat == 1) ? aLo : (mat == 2) ? bHi : bLo;
            int row0 = (mat < 2) ? aRow0 : bRow0;
            cpa16(base + mat * 16384u + SW64((r << 6) + (g << 4)),
                  srcm + (size_t)(row0 + r) * Kdim + cb + g * 8);
        }
    };

    load_chunk(0, 0); CP_COMMIT();
    load_chunk(1, 1); CP_COMMIT();

    float acc[4][8][4];
#pragma unroll
    for (int a = 0; a < 4; a++)
#pragma unroll
        for (int b = 0; b < 8; b++)
#pragma unroll
            for (int r = 0; r < 4; r++) acc[a][b][r] = 0.f;

    for (int c = 0; c < nCh; c++) {
        const int s = c & 1;
        if (c + 1 < nCh) asm volatile("cp.async.wait_group 1;" ::: "memory");
        else             asm volatile("cp.async.wait_group 0;" ::: "memory");
        __syncthreads();

        const uint32_t A_hi = stg[s], A_lo = stg[s] + 16384u;
        const uint32_t B_hi = stg[s] + 32768u, B_lo = stg[s] + 49152u;

#pragma unroll
        for (int ks = 0; ks < 2; ks++) {
            const int kbyte = ks * 32;               // 16 bf16 per step
            const int g = lane >> 3;
            uint32_t ah[4][4], al[4][4], bh[8][2], bl[8][2];
            {
                const int arow = (lane & 7) + ((g & 1) << 3);
                const int akc  = kbyte + ((g >> 1) << 4);
#pragma unroll
                for (int tn = 0; tn < 4; tn++) {
                    uint32_t off = SW64(((warp_i + tn * 16 + arow) << 6) + akc);
                    ldsm4(ah[tn], A_hi + off);
                    ldsm4(al[tn], A_lo + off);
                }
                const int brow = (lane & 7) + ((g >> 1) << 3);
                const int bkc  = kbyte + ((g & 1) << 4);
#pragma unroll
                for (int p = 0; p < 4; p++) {
                    uint32_t off = SW64(((warp_j + p * 16 + brow) << 6) + bkc);
                    uint32_t r4[4];
                    ldsm4(r4, B_hi + off);
                    bh[p * 2][0] = r4[0]; bh[p * 2][1] = r4[1];
                    bh[p * 2 + 1][0] = r4[2]; bh[p * 2 + 1][1] = r4[3];
                    ldsm4(r4, B_lo + off);
                    bl[p * 2][0] = r4[0]; bl[p * 2][1] = r4[1];
                    bl[p * 2 + 1][0] = r4[2]; bl[p * 2 + 1][1] = r4[3];
                }
            }
#pragma unroll
            for (int tn = 0; tn < 4; tn++)
#pragma unroll
                for (int tm = 0; tm < 8; tm++) {
                    mma_bf16(acc[tn][tm], ah[tn], bh[tm]);
                    mma_bf16(acc[tn][tm], al[tn], bh[tm]);
                    mma_bf16(acc[tn][tm], ah[tn], bl[tm]);
                }
        }
        __syncthreads();
        if (c + 2 < nCh) { load_chunk(c + 2, s); CP_COMMIT(); }
    }

    // epilogue: relu(C + bias[j]) -> bf16 hi/lo pairs
    const int li = lane >> 2;
    const int lj = (lane & 3) * 2;
#pragma unroll
    for (int tn = 0; tn < 4; tn++) {
#pragma unroll
        for (int tm = 0; tm < 8; tm++) {
            int i0 = warp_i + tn * 16 + li;
            int j0 = warp_j + tm * 8 + lj;
            float bj0 = bias[bRow0 + j0], bj1 = bias[bRow0 + j0 + 1];
#pragma unroll
            for (int h = 0; h < 2; h++) {
                float v0 = fmaxf(acc[tn][tm][h * 2 + 0] + bj0, 0.f);
                float v1 = fmaxf(acc[tn][tm][h * 2 + 1] + bj1, 0.f);
                __nv_bfloat16 h0 = __float2bfloat16(v0);
                __nv_bfloat16 h1 = __float2bfloat16(v1);
                __nv_bfloat162 hv; hv.x = h0; hv.y = h1;
                __nv_bfloat162 lv;
                lv.x = __float2bfloat16(v0 - __bfloat162float(h0));
                lv.y = __float2bfloat16(v1 - __bfloat162float(h1));
                size_t o = (size_t)(aRow0 + i0 + h * 8) * ost + bRow0 + j0;
                *(__nv_bfloat162*)&outHi[o] = hv;
                *(__nv_bfloat162*)&outLo[o] = lv;
            }
        }
    }
}

// ===================== mma.sync bf16x3 GEMM (128x128, unchanged) =====================
#define MMK_SMEM 131072

template<int MODE>
__global__ __launch_bounds__(512)
void mmk(const __nv_bfloat16* __restrict__ aHi, const __nv_bfloat16* __restrict__ aLo,
         const __nv_bfloat16* __restrict__ bHi, const __nv_bfloat16* __restrict__ bLo,
         const float* __restrict__ bias,
         __nv_bfloat16* __restrict__ outHi, __nv_bfloat16* __restrict__ outLo,
         float* __restrict__ outF, int Kdim, int ost, int Mreal)
{
    extern __shared__ __align__(1024) char smx[];
    const int tid  = threadIdx.x;
    const int wid  = tid >> 5, lane = tid & 31;
    const int nCh  = Kdim >> 6;

    const int aRow0 = (MODE == 1) ? blockIdx.x * 128 : 0;
    const int bRow0 = (MODE == 1) ? blockIdx.y * 128 : blockIdx.x * 128;

    const int warp_i = (wid >> 2) * 32;
    const int warp_j = (wid & 3) * 32;

    const uint32_t sbase = smem_u32(smx);
    const uint32_t stA[2] = { sbase, sbase + 65536u };

    auto load_chunk = [&](int c, int s) {
        const uint32_t base = stA[s];
        const size_t cb = (size_t)c * 64;
#pragma unroll
        for (int it = 0; it < 8; it++) {
            int idx = tid + it * 512;
            int mat = idx >> 10;
            int r   = (idx & 1023) >> 3;
            int g   = idx & 7;
            const __nv_bfloat16* srcm =
                (mat == 0) ? aHi : (mat == 1) ? aLo : (mat == 2) ? bHi : bLo;
            int row0 = (mat < 2) ? aRow0 : bRow0;
            cpa16(base + mat * 16384u + SW128((r << 7) + (g << 4)),
                  srcm + (size_t)(row0 + r) * Kdim + cb + g * 8);
        }
    };

    load_chunk(0, 0); CP_COMMIT();
    load_chunk(1, 1); CP_COMMIT();

    float acc[2][4][4];
#pragma unroll
    for (int a = 0; a < 2; a++)
#pragma unroll
        for (int b = 0; b < 4; b++)
#pragma unroll
            for (int r = 0; r < 4; r++) acc[a][b][r] = 0.f;

    for (int c = 0; c < nCh; c++) {
        const int s = c & 1;
        if (c + 1 < nCh) asm volatile("cp.async.wait_group 1;" ::: "memory");
        else             asm volatile("cp.async.wait_group 0;" ::: "memory");
        __syncthreads();

        const uint32_t A_hi = stA[s], A_lo = stA[s] + 16384u;
        const uint32_t B_hi = stA[s] + 32768u, B_lo = stA[s] + 49152u;

#pragma unroll
        for (int ks = 0; ks < 4; ks++) {
            const int kb = ks * 32;
            uint32_t ah[2][4], al[2][4], bh[4][2], bl[4][2];
            {
                const int g = lane >> 3;
                const int arow = (lane & 7) + ((g & 1) << 3);
                const int akc  = kb + ((g >> 1) << 4);
#pragma unroll
                for (int tn = 0; tn < 2; tn++) {
                    uint32_t off = SW128(((warp_i + tn * 16 + arow) << 7) + akc);
                    ldsm4(ah[tn], A_hi + off);
                    ldsm4(al[tn], A_lo + off);
                }
                const int brow = (lane & 7) + ((g >> 1) << 3);
                const int bkc  = kb + ((g & 1) << 4);
#pragma unroll
                for (int p = 0; p < 2; p++) {
                    uint32_t off = SW128(((warp_j + p * 16 + brow) << 7) + bkc);
                    uint32_t r4[4];
                    ldsm4(r4, B_hi + off);
                    bh[p * 2][0] = r4[0]; bh[p * 2][1] = r4[1];
                    bh[p * 2 + 1][0] = r4[2]; bh[p * 2 + 1][1] = r4[3];
                    ldsm4(r4, B_lo + off);
                    bl[p * 2][0] = r4[0]; bl[p * 2][1] = r4[1];
                    bl[p * 2 + 1][0] = r4[2]; bl[p * 2 + 1][1] = r4[3];
                }
            }
#pragma unroll
            for (int tn = 0; tn < 2; tn++)
#pragma unroll
                for (int tm = 0; tm < 4; tm++) {
                    mma_bf16(acc[tn][tm], ah[tn], bh[tm]);
                    mma_bf16(acc[tn][tm], al[tn], bh[tm]);
                    mma_bf16(acc[tn][tm], ah[tn], bl[tm]);
                }
        }
        __syncthreads();
        if (c + 2 < nCh) { load_chunk(c + 2, s); CP_COMMIT(); }
    }

    const int li = lane >> 2;
    const int lj = (lane & 3) * 2;
#pragma unroll
    for (int tn = 0; tn < 2; tn++) {
#pragma unroll
        for (int tm = 0; tm < 4; tm++) {
            int i0 = warp_i + tn * 16 + li;
            int j0 = warp_j + tm * 8 + lj;
            if (MODE == 1) {
                float bj0 = bias[bRow0 + j0], bj1 = bias[bRow0 + j0 + 1];
#pragma unroll
                for (int h = 0; h < 2; h++) {
                    float v0 = fmaxf(acc[tn][tm][h * 2 + 0] + bj0, 0.f);
                    float v1 = fmaxf(acc[tn][tm][h * 2 + 1] + bj1, 0.f);
                    __nv_bfloat16 h0 = __float2bfloat16(v0);
                    __nv_bfloat16 h1 = __float2bfloat16(v1);
                    __nv_bfloat162 hv; hv.x = h0; hv.y = h1;
                    __nv_bfloat162 lv;
                    lv.x = __float2bfloat16(v0 - __bfloat162float(h0));
                    lv.y = __float2bfloat16(v1 - __bfloat162float(h1));
                    size_t o = (size_t)(aRow0 + i0 + h * 8) * ost + bRow0 + j0;
                    *(__nv_bfloat162*)&outHi[o] = hv;
                    *(__nv_bfloat162*)&outLo[o] = lv;
                }
            } else {
#pragma unroll
                for (int h = 0; h < 2; h++) {
                    int i = i0 + h * 8;
                    if (i < Mreal) {
                        float bi = bias[i];
                        float2 v = make_float2(acc[tn][tm][h * 2 + 0] + bi,
                                               acc[tn][tm][h * 2 + 1] + bi);
                        *(float2*)&outF[(size_t)i * ost + bRow0 + j0] = v;
                    }
                }
            }
        }
    }
}

// ===================== attention (unchanged from R16 passing) =====================
#define ATT_SMEM 201216

__global__ __launch_bounds__(512)
void attn_kernel(const __nv_bfloat16* __restrict__ qhi, const __nv_bfloat16* __restrict__ qlo,
                 const __nv_bfloat16* __restrict__ khi, const __nv_bfloat16* __restrict__ klo,
                 const float* __restrict__ q2g, const float* __restrict__ k2g,
                 const int* __restrict__ mask,
                 float* __restrict__ attn_out, float* __restrict__ logp_out)
{
    extern __shared__ __align__(1024) char smraw[];
    const uint32_t sbase = smem_u32(smraw);
    const uint32_t QHI = sbase, QLO = sbase + 32768u;
    const uint32_t KST = sbase + 65536u;
    float* q2s   = (float*)(smraw + 196608);
    float* k2s   = (float*)(smraw + 197120);
    int*   maskS = (int*)  (smraw + 199168);

    const int b   = blockIdx.y;
    const int q0  = blockIdx.x * 128;
    const int tid = threadIdx.x;
    const int wid = tid >> 5, lane = tid & 31;
    const int nq0 = b * 2048 + q0;
    const int nk0 = b * 512;

#pragma unroll
    for (int it = 0; it < 8; it++) {
        int idx = tid + it * 512;
        int half = idx >> 11;
        int rem  = idx & 2047;
        int h    = rem >> 10;
        int rr   = (rem >> 3) & 127;
        int g    = rem & 7;
        const __nv_bfloat16* src = (half ? qlo : qhi);
        cpa16((half ? QLO : QHI) + h * 16384u + SW128((rr << 7) + (g << 4)),
              src + (size_t)(nq0 + rr) * 128 + h * 64 + g * 8);
    }
    auto load_k = [&](int kc, int s) {
        const uint32_t base = KST + (uint32_t)s * 65536u;
#pragma unroll
        for (int it = 0; it < 8; it++) {
            int idx = tid + it * 512;
            int half = idx >> 11;
            int rem  = idx & 2047;
            int h    = rem >> 10;
            int rr   = (rem >> 3) & 127;
            int g    = rem & 7;
            const __nv_bfloat16* src = (half ? klo : khi);
            cpa16(base + half * 32768u + h * 16384u + SW128((rr << 7) + (g << 4)),
                  src + (size_t)(nk0 + kc * 128 + rr) * 128 + h * 64 + g * 8);
        }
    };
    load_k(0, 0); CP_COMMIT();
    load_k(1, 1); CP_COMMIT();

    if (tid < 128) q2s[tid] = q2g[nq0 + tid];
    k2s[tid]   = k2g[nk0 + tid];
    maskS[tid] = mask[nk0 + tid];

    const int li = lane >> 2;
    const int lj = (lane & 3) * 2;
    const int warp_i = (wid >> 2) * 32;
    const int wj     = (wid & 3) * 32;

    const size_t rowbase = ((size_t)b * 2048 + q0) * 512;

    for (int kc = 0; kc < 4; kc++) {
        const int s = kc & 1;
        if (kc + 1 < 4) asm volatile("cp.async.wait_group 1;" ::: "memory");
        else            asm volatile("cp.async.wait_group 0;" ::: "memory");
        __syncthreads();

        float acc[2][4][4];
#pragma unroll
        for (int a = 0; a < 2; a++)
#pragma unroll
            for (int c2 = 0; c2 < 4; c2++)
#pragma unroll
                for (int r = 0; r < 4; r++) acc[a][c2][r] = 0.f;

        const uint32_t KB = KST + (uint32_t)s * 65536u;
#pragma unroll
        for (int ks = 0; ks < 8; ks++) {
            const int h  = ks >> 2;
            const int kb = (ks & 3) * 32;
            const int g  = lane >> 3;
            uint32_t ah[2][4], al[2][4], bh[4][2], bl[4][2];
            {
                const int arow = (lane & 7) + ((g & 1) << 3);
                const int akc  = kb + ((g >> 1) << 4);
#pragma unroll
                for (int tn = 0; tn < 2; tn++) {
                    uint32_t offA = (uint32_t)h * 16384u
                                  + SW128(((warp_i + tn * 16 + arow) << 7) + akc);
                    ldsm4(ah[tn], QHI + offA);
                    ldsm4(al[tn], QLO + offA);
                }
                const int brow = (lane & 7) + ((g >> 1) << 3);
                const int bkc  = kb + ((g & 1) << 4);
#pragma unroll
                for (int p = 0; p < 2; p++) {
                    uint32_t off = (uint32_t)h * 16384u
                                 + SW128(((wj + p * 16 + brow) << 7) + bkc);
                    uint32_t r4[4];
                    ldsm4(r4, KB + off);
                    bh[p * 2][0] = r4[0]; bh[p * 2][1] = r4[1];
                    bh[p * 2 + 1][0] = r4[2]; bh[p * 2 + 1][1] = r4[3];
                    ldsm4(r4, KB + 32768u + off);
                    bl[p * 2][0] = r4[0]; bl[p * 2][1] = r4[1];
                    bl[p * 2 + 1][0] = r4[2]; bl[p * 2 + 1][1] = r4[3];
                }
            }
#pragma unroll
            for (int tn = 0; tn < 2; tn++)
#pragma unroll
                for (int tm = 0; tm < 4; tm++) {
                    mma_bf16(acc[tn][tm], ah[tn], bh[tm]);
                    mma_bf16(acc[tn][tm], al[tn], bh[tm]);
                    mma_bf16(acc[tn][tm], ah[tn], bl[tm]);
                }
        }
        __syncthreads();
        if (kc + 2 < 4) { load_k(kc + 2, s); CP_COMMIT(); }

#pragma unroll
        for (int tn = 0; tn < 2; tn++)
#pragma unroll
            for (int tm = 0; tm < 4; tm++)
#pragma unroll
                for (int hh = 0; hh < 2; hh++) {
                    int i  = warp_i + tn * 16 + hh * 8 + li;
                    int kg = kc * 128 + wj + tm * 8 + lj;
                    float q2v = q2s[i];
                    float d0 = q2v + k2s[kg]     - 2.f * acc[tn][tm][hh * 2 + 0];
                    float d1 = q2v + k2s[kg + 1] - 2.f * acc[tn][tm][hh * 2 + 1];
                    d0 = sqrt_fast(fmaxf(d0, 1e-12f));
                    d1 = sqrt_fast(fmaxf(d1, 1e-12f));
                    if (maskS[kg]     == 0) d0 = -FLT_MAX;
                    if (maskS[kg + 1] == 0) d1 = -FLT_MAX;
                    *(float2*)&logp_out[rowbase + (size_t)i * 512 + kg] = make_float2(d0, d1);
                }
    }

    __threadfence_block();
    __syncthreads();

#pragma unroll
    for (int r = 0; r < 8; r++) {
        int qi = wid * 8 + r;
        const float* rowp = logp_out + rowbase + (size_t)qi * 512;
        float vals[16];
#pragma unroll
        for (int j = 0; j < 4; j++)
            *(float4*)&vals[j * 4] = *(const float4*)&rowp[lane * 4 + j * 128];
        float mx = -FLT_MAX;
#pragma unroll
        for (int j = 0; j < 16; j++) mx = fmaxf(mx, vals[j]);
#pragma unroll
        for (int off = 16; off; off >>= 1)
            mx = fmaxf(mx, __shfl_xor_sync(0xffffffffu, mx, off));
        float s = 0.f;
#pragma unroll
        for (int j = 0; j < 16; j++) { vals[j] = exp_fast(vals[j] - mx); s += vals[j]; }
#pragma unroll
        for (int off = 16; off; off >>= 1)
            s += __shfl_xor_sync(0xffffffffu, s, off);
        float inv = 1.f / s;
        float* rowo = attn_out + rowbase + (size_t)qi * 512;
#pragma unroll
        for (int j = 0; j < 4; j++) {
            float4 o;
            o.x = vals[j * 4 + 0] * inv; o.y = vals[j * 4 + 1] * inv;
            o.z = vals[j * 4 + 2] * inv; o.w = vals[j * 4 + 3] * inv;
            *(float4*)&rowo[lane * 4 + j * 128] = o;
        }
    }
}

// ---------------------------------------------------------------------------
extern "C" void kernel_launch(void* const* d_in, const int* in_sizes, int n_in,
                              void* d_out, int out_size)
{
    const float* queries = (const float*)d_in[0];
    const float* keys    = (const float*)d_in[1];
    const int*   mask    = (const int*)d_in[2];
    const float* kw1 = (const float*)d_in[3];
    const float* kb1 = (const float*)d_in[4];
    const float* kw2 = (const float*)d_in[5];
    const float* kb2 = (const float*)d_in[6];
    const float* qw1 = (const float*)d_in[7];
    const float* qb1 = (const float*)d_in[8];
    const float* qw2 = (const float*)d_in[9];
    const float* qb2 = (const float*)d_in[10];
    const float* qw3 = (const float*)d_in[11];
    const float* qb3 = (const float*)d_in[12];

    __nv_bfloat16 *bthi, *btlo, *w1hi, *w1lo, *hthi, *htlo, *w2hi, *w2lo;
    __nv_bfloat16 *btqhi, *btqlo, *qw1hi, *qw1lo, *q1hi, *q1lo;
    __nv_bfloat16 *qw2hi, *qw2lo, *q2hi, *q2lo, *qw3hi, *qw3lo;
    __nv_bfloat16 *qfthi, *qftlo, *kfthi, *kftlo;
    float *kf, *qf, *qb1p, *qb2p, *qb3p, *kb2p, *q2n, *k2n;
    cudaGetSymbolAddress((void**)&bthi, g_Bthi);
    cudaGetSymbolAddress((void**)&btlo, g_Btlo);
    cudaGetSymbolAddress((void**)&w1hi, g_w1hi);
    cudaGetSymbolAddress((void**)&w1lo, g_w1lo);
    cudaGetSymbolAddress((void**)&hthi, g_hThi);
    cudaGetSymbolAddress((void**)&htlo, g_hTlo);
    cudaGetSymbolAddress((void**)&w2hi, g_w2hi);
    cudaGetSymbolAddress((void**)&w2lo, g_w2lo);
    cudaGetSymbolAddress((void**)&btqhi, g_BtQhi);
    cudaGetSymbolAddress((void**)&btqlo, g_BtQlo);
    cudaGetSymbolAddress((void**)&qw1hi, g_qw1hi);
    cudaGetSymbolAddress((void**)&qw1lo, g_qw1lo);
    cudaGetSymbolAddress((void**)&q1hi, g_q1hi);
    cudaGetSymbolAddress((void**)&q1lo, g_q1lo);
    cudaGetSymbolAddress((void**)&qw2hi, g_qw2hi);
    cudaGetSymbolAddress((void**)&qw2lo, g_qw2lo);
    cudaGetSymbolAddress((void**)&q2hi, g_q2hi);
    cudaGetSymbolAddress((void**)&q2lo, g_q2lo);
    cudaGetSymbolAddress((void**)&qw3hi, g_qw3hi);
    cudaGetSymbolAddress((void**)&qw3lo, g_qw3lo);
    cudaGetSymbolAddress((void**)&qfthi, g_qfThi);
    cudaGetSymbolAddress((void**)&qftlo, g_qfTlo);
    cudaGetSymbolAddress((void**)&kfthi, g_kfThi);
    cudaGetSymbolAddress((void**)&kftlo, g_kfTlo);
    cudaGetSymbolAddress((void**)&kf, g_kf);
    cudaGetSymbolAddress((void**)&qf, g_qf);
    cudaGetSymbolAddress((void**)&qb1p, g_qb1p);
    cudaGetSymbolAddress((void**)&qb2p, g_qb2p);
    cudaGetSymbolAddress((void**)&qb3p, g_qb3p);
    cudaGetSymbolAddress((void**)&kb2p, g_kb2p);
    cudaGetSymbolAddress((void**)&q2n, g_q2n);
    cudaGetSymbolAddress((void**)&k2n, g_k2n);

    cudaFuncSetAttribute(mmk<1>, cudaFuncAttributeMaxDynamicSharedMemorySize, MMK_SMEM);
    cudaFuncSetAttribute(mmk<2>, cudaFuncAttributeMaxDynamicSharedMemorySize, MMK_SMEM);
    cudaFuncSetAttribute(mmk_big, cudaFuncAttributeMaxDynamicSharedMemorySize, MMKB_SMEM);
    cudaFuncSetAttribute(attn_kernel, cudaFuncAttributeMaxDynamicSharedMemorySize, ATT_SMEM);

    // ---- prep ----
    split_pad2<<<(1024 * 1536) / 256, 256>>>(kw1, w1hi, w1lo, 1024, 1536, 1536, 1024 * 1536);
    split_pad2<<<(128 * 1024) / 256, 256>>>(kw2, w2hi, w2lo, 80, 1024, 1024, 128 * 1024);
    split_pad2<<<(256 * 256) / 256, 256>>>(qw1, qw1hi, qw1lo, 160, 240, 256, 256 * 256);
    split_pad2<<<(128 * 256) / 256, 256>>>(qw2, qw2hi, qw2lo, 80, 160, 256, 128 * 256);
    split_pad2<<<(128 * 128) / 256, 256>>>(qw3, qw3hi, qw3lo, 80, 80, 128, 128 * 128);
    pad_bias<<<1, 256>>>(qb1, qb1p, 160, 256);
    pad_bias<<<1, 256>>>(qb2, qb2p, 80, 128);
    pad_bias<<<1, 256>>>(qb3, qb3p, 80, 128);
    pad_bias<<<1, 256>>>(kb2, kb2p, 80, 128);
    build_Bt<<<dim3(64, 8), 256>>>(keys, bthi, btlo);
    build_BtQ<<<256, 256>>>(queries, btqhi, btqlo);

    // ---- K path (GEMM1 = big-tile 256x256, single wave) ----
    mmk_big<<<dim3(32, 4), 512, MMKB_SMEM>>>(bthi, btlo, w1hi, w1lo, kb1,
                                             hthi, htlo, 1536, 1024);
    mmk<2><<<dim3(64, 1), 512, MMK_SMEM>>>(w2hi, w2lo, hthi, htlo, kb2p,
                                           nullptr, nullptr, kf, 1024, NK, 80);

    // ---- Q path ----
    mmk<1><<<dim3(256, 2), 512, MMK_SMEM>>>(btqhi, btqlo, qw1hi, qw1lo, qb1p,
                                            q1hi, q1lo, nullptr, 256, 256, 0);
    mmk<1><<<dim3(256, 1), 512, MMK_SMEM>>>(q1hi, q1lo, qw2hi, qw2lo, qb2p,
                                            q2hi, q2lo, nullptr, 256, 128, 0);
    mmk<2><<<dim3(256, 1), 512, MMK_SMEM>>>(qw3hi, qw3lo, q2hi, q2lo, qb3p,
                                            nullptr, nullptr, qf, 128, NQ, 80);

    // ---- transpose/split features + norms for attention ----
    cvtT<<<NQ / 128, 256>>>(qf, NQ, qfthi, qftlo, q2n);
    cvtT<<<NK / 128, 256>>>(kf, NK, kfthi, kftlo, k2n);

    // ---- attention + softmax (128 q-rows per block) ----
    float* attn = (float*)d_out;
    float* logp = attn + (size_t)16 * 2048 * 512;
    attn_kernel<<<dim3(16, 16), 512, ATT_SMEM>>>(qfthi, qftlo, kfthi, kftlo,
                                                 q2n, k2n, mask, attn, logp);
}